// round 4
// baseline (speedup 1.0000x reference)
#include <cuda_runtime.h>
#include <cuda_bf16.h>
#include <math.h>

// ---------------- model constants ----------------
#define Vv 50257
#define VP 50304            // padded vocab (multiple of 128)
#define Dd 768
#define Hh 12
#define HD 64
#define Tt 1024
#define Ll 6
#define Bb 4
#define BT (Bb*Tt)          // 4096
#define FF (4*Dd)           // 3072

#define BM 128
#define BN 128
#define BKK 16

// ---------------- scratch (static device arrays; no allocation) ----------------
__device__ float g_x   [BT*Dd];
__device__ float g_x2  [BT*Dd];
__device__ float g_q   [BT*Dd];
__device__ float g_k   [BT*Dd];
__device__ float g_v   [BT*Dd];
__device__ float g_y   [BT*Dd];
__device__ float g_ff1 [BT*FF];
__device__ float g_rl  [BT];
__device__ float g_wpad[(size_t)Dd*VP];   // padded, pre-tf32 head weights

__device__ __forceinline__ float to_tf32(float x) {
    float y;
    asm("cvt.rna.tf32.f32 %0, %1;" : "=f"(y) : "f"(x));
    return y;
}

// ---------------- embedding ----------------
__global__ void embed_kernel(const int* __restrict__ idx,
                             const float* __restrict__ tok,
                             const float* __restrict__ pos,
                             float* __restrict__ x) {
    int r = blockIdx.x;
    int t = r & (Tt - 1);
    int token = idx[r];
    const float* tr = tok + (size_t)token * Dd;
    const float* pr = pos + (size_t)t * Dd;
    float* xr = x + (size_t)r * Dd;
    for (int c = threadIdx.x; c < Dd; c += blockDim.x)
        xr[c] = tr[c] + pr[c];
}

// ---------------- pad + pre-convert head weights ----------------
__global__ void padw_kernel(const float* __restrict__ w, float* __restrict__ wp) {
    int kk = blockIdx.x;             // 0..767
    const float* src = w + (size_t)kk * Vv;
    float* dst = wp + (size_t)kk * VP;
    for (int n = threadIdx.x; n < VP; n += blockDim.x)
        dst[n] = (n < Vv) ? to_tf32(src[n]) : 0.f;
}

// ---------------- TF32 tensor-core GEMM core ----------------
// C(row0:+128, col0:+128) += A(MxK) @ B(KxBstride);  store guard col<N.
// 256 threads = 8 warps (2M x 4N), warp tile 64x32, mma.m16n8k8.tf32.
// Register-staged prefetch: gmem loads for tile k0+BK issued before compute(k0).
template<int EPI>
__device__ __forceinline__ void gemm_core(
    const float* __restrict__ A, const float* __restrict__ Bm,
    const float* __restrict__ bias, float* __restrict__ C,
    int N, int K, int Bstride, int row0, int col0)
{
    __shared__ float As[BKK][BM + 4];   // As[k][m]
    __shared__ float Bs[BKK][BN + 4];   // Bs[k][n]

    int t    = threadIdx.x;
    int wid  = t >> 5;
    int lane = t & 31;
    int g    = lane >> 2;
    int tig  = lane & 3;
    int m0w  = (wid & 1) * 64;
    int n0w  = (wid >> 1) * 32;

    const bool vec_ok = ((col0 + BN) <= Bstride) && ((Bstride & 3) == 0);

    // per-thread load coordinates
    const int arow0 = (t + 0)   >> 2, aseg0 = ((t + 0)   & 3) * 4;
    const int arow1 = (t + 256) >> 2, aseg1 = ((t + 256) & 3) * 4;
    const int bkr0  = (t + 0)   >> 5, bcs0  = ((t + 0)   & 31) * 4;
    const int bkr1  = (t + 256) >> 5, bcs1  = ((t + 256) & 31) * 4;

    float4 aS0, aS1;          // A staging
    float4 bS0, bS1;          // B staging (vec)
    float  bSs[8];            // B staging (scalar)

    float acc[4][4][4];
#pragma unroll
    for (int im = 0; im < 4; im++)
#pragma unroll
        for (int in = 0; in < 4; in++)
#pragma unroll
            for (int c = 0; c < 4; c++) acc[im][in][c] = 0.f;

    // ---- load helpers ----
    auto loadA = [&](int k0) {
        aS0 = *(const float4*)(A + (size_t)(row0 + arow0) * K + k0 + aseg0);
        aS1 = *(const float4*)(A + (size_t)(row0 + arow1) * K + k0 + aseg1);
    };
    auto loadB = [&](int k0) {
        if (vec_ok) {
            bS0 = *(const float4*)(Bm + (size_t)(k0 + bkr0) * Bstride + col0 + bcs0);
            bS1 = *(const float4*)(Bm + (size_t)(k0 + bkr1) * Bstride + col0 + bcs1);
        } else {
#pragma unroll
            for (int i = 0; i < 8; i++) {
                int e = t + i * 256;
                int kr = e >> 7, c = e & 127;
                int col = col0 + c;
                bSs[i] = (col < Bstride) ? Bm[(size_t)(k0 + kr) * Bstride + col] : 0.f;
            }
        }
    };
    auto storeAB = [&]() {
        As[aseg0 + 0][arow0] = to_tf32(aS0.x);
        As[aseg0 + 1][arow0] = to_tf32(aS0.y);
        As[aseg0 + 2][arow0] = to_tf32(aS0.z);
        As[aseg0 + 3][arow0] = to_tf32(aS0.w);
        As[aseg1 + 0][arow1] = to_tf32(aS1.x);
        As[aseg1 + 1][arow1] = to_tf32(aS1.y);
        As[aseg1 + 2][arow1] = to_tf32(aS1.z);
        As[aseg1 + 3][arow1] = to_tf32(aS1.w);
        if (vec_ok) {
            Bs[bkr0][bcs0 + 0] = to_tf32(bS0.x);
            Bs[bkr0][bcs0 + 1] = to_tf32(bS0.y);
            Bs[bkr0][bcs0 + 2] = to_tf32(bS0.z);
            Bs[bkr0][bcs0 + 3] = to_tf32(bS0.w);
            Bs[bkr1][bcs1 + 0] = to_tf32(bS1.x);
            Bs[bkr1][bcs1 + 1] = to_tf32(bS1.y);
            Bs[bkr1][bcs1 + 2] = to_tf32(bS1.z);
            Bs[bkr1][bcs1 + 3] = to_tf32(bS1.w);
        } else {
#pragma unroll
            for (int i = 0; i < 8; i++) {
                int e = t + i * 256;
                int kr = e >> 7, c = e & 127;
                Bs[kr][c] = to_tf32(bSs[i]);
            }
        }
    };
    auto compute = [&]() {
#pragma unroll
        for (int ks = 0; ks < BKK; ks += 8) {
            unsigned af[4][4], bf[4][2];
#pragma unroll
            for (int im = 0; im < 4; im++) {
                int m = m0w + im * 16 + g;
                af[im][0] = __float_as_uint(As[ks + tig    ][m    ]);
                af[im][1] = __float_as_uint(As[ks + tig    ][m + 8]);
                af[im][2] = __float_as_uint(As[ks + tig + 4][m    ]);
                af[im][3] = __float_as_uint(As[ks + tig + 4][m + 8]);
            }
#pragma unroll
            for (int in = 0; in < 4; in++) {
                int n = n0w + in * 8 + g;
                bf[in][0] = __float_as_uint(Bs[ks + tig    ][n]);
                bf[in][1] = __float_as_uint(Bs[ks + tig + 4][n]);
            }
#pragma unroll
            for (int im = 0; im < 4; im++)
#pragma unroll
                for (int in = 0; in < 4; in++) {
                    asm volatile(
                        "mma.sync.aligned.m16n8k8.row.col.f32.tf32.tf32.f32 "
                        "{%0,%1,%2,%3},{%4,%5,%6,%7},{%8,%9},{%0,%1,%2,%3};"
                        : "+f"(acc[im][in][0]), "+f"(acc[im][in][1]),
                          "+f"(acc[im][in][2]), "+f"(acc[im][in][3])
                        : "r"(af[im][0]), "r"(af[im][1]), "r"(af[im][2]), "r"(af[im][3]),
                          "r"(bf[in][0]), "r"(bf[in][1]));
                }
        }
    };

    // ---- pipelined mainloop ----
    loadA(0); loadB(0);
    storeAB();
    __syncthreads();
    for (int k0 = BKK; k0 < K; k0 += BKK) {
        loadA(k0); loadB(k0);     // prefetch next tile (in flight during compute)
        compute();
        __syncthreads();
        storeAB();
        __syncthreads();
    }
    compute();

    // ---- epilogue ----
#pragma unroll
    for (int im = 0; im < 4; im++) {
        int r_lo = row0 + m0w + im * 16 + g;
        int r_hi = r_lo + 8;
#pragma unroll
        for (int in = 0; in < 4; in++) {
            int c_lo = col0 + n0w + in * 8 + 2 * tig;
            int c_hi = c_lo + 1;
            float v0 = acc[im][in][0], v1 = acc[im][in][1];
            float v2 = acc[im][in][2], v3 = acc[im][in][3];
            if (EPI >= 1) {
                if (c_lo < N) { v0 += bias[c_lo]; v2 += bias[c_lo]; }
                if (c_hi < N) { v1 += bias[c_hi]; v3 += bias[c_hi]; }
            }
            if (EPI == 2) {
                v0 = fmaxf(v0, 0.f); v1 = fmaxf(v1, 0.f);
                v2 = fmaxf(v2, 0.f); v3 = fmaxf(v3, 0.f);
            }
            size_t blo = (size_t)r_lo * N;
            size_t bhi = (size_t)r_hi * N;
            if (c_lo < N) { C[blo + c_lo] = v0; C[bhi + c_lo] = v2; }
            if (c_hi < N) { C[blo + c_hi] = v1; C[bhi + c_hi] = v3; }
        }
    }
}

template<int EPI>
__global__ __launch_bounds__(256)
void tgemm_kernel(const float* __restrict__ A, const float* __restrict__ Bm,
                  const float* __restrict__ bias, float* __restrict__ C,
                  int N, int K, int Bstride) {
    gemm_core<EPI>(A, Bm, bias, C, N, K, Bstride,
                   blockIdx.y * BM, blockIdx.x * BN);
}

// fused QKV: grid (18, 32); blockIdx.x selects {Wq,Wk,Wv} x 6 col-tiles
__global__ __launch_bounds__(256)
void qkv_kernel(const float* __restrict__ x,
                const float* __restrict__ wq, const float* __restrict__ wk,
                const float* __restrict__ wv,
                float* __restrict__ q, float* __restrict__ k, float* __restrict__ v) {
    int ct  = blockIdx.x;          // 0..17
    int mat = ct / 6;
    int c   = ct % 6;
    const float* B = (mat == 0) ? wq : (mat == 1) ? wk : wv;
    float*       C = (mat == 0) ? q  : (mat == 1) ? k  : v;
    gemm_core<0>(x, B, nullptr, C, Dd, Dd, Dd, blockIdx.y * BM, c * BN);
}

// ---------------- causal flash attention ----------------
__global__ __launch_bounds__(128)
void attn_kernel(const float* __restrict__ q, const float* __restrict__ k,
                 const float* __restrict__ v, float* __restrict__ y) {
    __shared__ float Qs[64][65];
    __shared__ float Ks[32][65];
    __shared__ float Vs[32][65];
    __shared__ float Ss[64][33];
    __shared__ float mrow[64], lrow[64], cfac[64];

    int t  = threadIdx.x;
    int qt = blockIdx.x;
    int h  = blockIdx.y;
    int b  = blockIdx.z;
    int q0 = qt * 64;

    for (int idx = t; idx < 64 * 64; idx += 128) {
        int r = idx >> 6, c = idx & 63;
        Qs[r][c] = q[((size_t)(b * Tt + q0 + r)) * Dd + h * HD + c];
    }
    if (t < 64) { mrow[t] = -1e30f; lrow[t] = 0.f; }

    float acc[32];
#pragma unroll
    for (int d = 0; d < 32; d++) acc[d] = 0.f;

    int qi_own = t & 63;
    int hoff   = (t >> 6) * 32;

    int ntiles = (q0 + 64) / 32;
    __syncthreads();

    for (int j = 0; j < ntiles; j++) {
        int s0 = j * 32;
        for (int idx = t; idx < 32 * 64; idx += 128) {
            int r = idx >> 6, c = idx & 63;
            size_t gg = ((size_t)(b * Tt + s0 + r)) * Dd + h * HD + c;
            Ks[r][c] = k[gg];
            Vs[r][c] = v[gg];
        }
        __syncthreads();

        for (int idx = t; idx < 64 * 32; idx += 128) {
            int qi = idx >> 5, kj = idx & 31;
            float sum = 0.f;
#pragma unroll
            for (int c = 0; c < 64; c++) sum += Qs[qi][c] * Ks[kj][c];
            sum *= 0.125f;
            if (s0 + kj > q0 + qi) sum = -1e30f;
            Ss[qi][kj] = sum;
        }
        __syncthreads();

        if (t < 64) {
            int qi = t;
            float m = mrow[qi];
            float nm = m;
#pragma unroll
            for (int kj = 0; kj < 32; kj++) nm = fmaxf(nm, Ss[qi][kj]);
            float corr = __expf(m - nm);
            float sum = 0.f;
#pragma unroll
            for (int kj = 0; kj < 32; kj++) {
                float p = __expf(Ss[qi][kj] - nm);
                Ss[qi][kj] = p;
                sum += p;
            }
            lrow[qi] = lrow[qi] * corr + sum;
            mrow[qi] = nm;
            cfac[qi] = corr;
        }
        __syncthreads();

        float corr = cfac[qi_own];
#pragma unroll
        for (int d = 0; d < 32; d++) acc[d] *= corr;
#pragma unroll
        for (int kj = 0; kj < 32; kj++) {
            float p = Ss[qi_own][kj];
#pragma unroll
            for (int d = 0; d < 32; d++)
                acc[d] += p * Vs[kj][hoff + d];
        }
        __syncthreads();
    }

    float inv = 1.f / lrow[qi_own];
    size_t base = ((size_t)(b * Tt + q0 + qi_own)) * Dd + h * HD + hoff;
#pragma unroll
    for (int d = 0; d < 32; d++)
        y[base + d] = acc[d] * inv;
}

// ---------------- residual + LayerNorm ----------------
__global__ __launch_bounds__(256)
void ln_res_kernel(const float* __restrict__ a, const float* __restrict__ b,
                   const float* __restrict__ g, const float* __restrict__ be,
                   float* __restrict__ out) {
    __shared__ float buf[Dd];
    __shared__ float red[256];
    int r = blockIdx.x;
    int t = threadIdx.x;
    const float* ar = a + (size_t)r * Dd;
    const float* br = b + (size_t)r * Dd;

    float s = 0.f;
    for (int c = t; c < Dd; c += 256) {
        float vv = ar[c] + br[c];
        buf[c] = vv;
        s += vv;
    }
    red[t] = s; __syncthreads();
    for (int o = 128; o > 0; o >>= 1) { if (t < o) red[t] += red[t + o]; __syncthreads(); }
    float mu = red[0] / (float)Dd;
    __syncthreads();

    float s2 = 0.f;
    for (int c = t; c < Dd; c += 256) {
        float d = buf[c] - mu;
        s2 += d * d;
    }
    red[t] = s2; __syncthreads();
    for (int o = 128; o > 0; o >>= 1) { if (t < o) red[t] += red[t + o]; __syncthreads(); }
    float rstd = rsqrtf(red[0] / (float)Dd + 1e-5f);

    float* orr = out + (size_t)r * Dd;
    for (int c = t; c < Dd; c += 256)
        orr[c] = (buf[c] - mu) * rstd * g[c] + be[c];
}

// ---------------- per-row cross-entropy ----------------
__global__ __launch_bounds__(256)
void rowloss_kernel(const float* __restrict__ logits, const int* __restrict__ tgt,
                    float* __restrict__ rl) {
    __shared__ float sm[256], sl[256];
    int r = blockIdx.x;
    int t = threadIdx.x;
    const float* lg = logits + (size_t)r * Vv;

    float m = -1e30f, l = 0.f;
    for (int c = t; c < Vv; c += 256) {
        float x = lg[c];
        if (x > m) { l = l * __expf(m - x) + 1.f; m = x; }
        else       { l += __expf(x - m); }
    }
    sm[t] = m; sl[t] = l; __syncthreads();
    for (int o = 128; o > 0; o >>= 1) {
        if (t < o) {
            float m1 = sm[t], m2 = sm[t + o];
            float M = fmaxf(m1, m2);
            sl[t] = sl[t] * __expf(m1 - M) + sl[t + o] * __expf(m2 - M);
            sm[t] = M;
        }
        __syncthreads();
    }
    if (t == 0)
        rl[r] = (sm[0] + logf(sl[0])) - lg[tgt[r]];
}

__global__ __launch_bounds__(256)
void meanloss_kernel(const float* __restrict__ rl, float* __restrict__ out) {
    __shared__ float red[256];
    int t = threadIdx.x;
    float s = 0.f;
    for (int i = t; i < BT; i += 256) s += rl[i];
    red[t] = s; __syncthreads();
    for (int o = 128; o > 0; o >>= 1) { if (t < o) red[t] += red[t + o]; __syncthreads(); }
    if (t == 0) out[0] = red[0] / (float)BT;
}

// ---------------- launch ----------------
extern "C" void kernel_launch(void* const* d_in, const int* in_sizes, int n_in,
                              void* d_out, int out_size) {
    const int*   idx    = (const int*)  d_in[0];
    const int*   tgt    = (const int*)  d_in[1];
    const float* tok    = (const float*)d_in[2];
    const float* pos    = (const float*)d_in[3];
    const float* Wq     = (const float*)d_in[4];
    const float* Wk     = (const float*)d_in[5];
    const float* Wv     = (const float*)d_in[6];
    const float* ln1g   = (const float*)d_in[7];
    const float* ln1b   = (const float*)d_in[8];
    const float* W1     = (const float*)d_in[9];
    const float* b1     = (const float*)d_in[10];
    const float* W2     = (const float*)d_in[11];
    const float* b2     = (const float*)d_in[12];
    const float* ln2g   = (const float*)d_in[13];
    const float* ln2b   = (const float*)d_in[14];
    const float* headw  = (const float*)d_in[15];
    const float* headb  = (const float*)d_in[16];
    float* out = (float*)d_out;

    float *x, *x2, *q, *k, *v, *y, *ff1, *rl, *wpad;
    cudaGetSymbolAddress((void**)&x,    g_x);
    cudaGetSymbolAddress((void**)&x2,   g_x2);
    cudaGetSymbolAddress((void**)&q,    g_q);
    cudaGetSymbolAddress((void**)&k,    g_k);
    cudaGetSymbolAddress((void**)&v,    g_v);
    cudaGetSymbolAddress((void**)&y,    g_y);
    cudaGetSymbolAddress((void**)&ff1,  g_ff1);
    cudaGetSymbolAddress((void**)&rl,   g_rl);
    cudaGetSymbolAddress((void**)&wpad, g_wpad);

    embed_kernel<<<BT, 256>>>(idx, tok, pos, x);
    padw_kernel<<<Dd, 256>>>(headw, wpad);   // independent of layer stack

    dim3 gQKV(18, BT / 128);
    dim3 gD(Dd / 128, BT / 128);             // 6 x 32
    dim3 gF(FF / 128, BT / 128);             // 24 x 32
    dim3 gV(VP / 128, BT / 128);             // 393 x 32

    for (int l = 0; l < Ll; l++) {
        const float* wq = Wq + (size_t)l * Dd * Dd;
        const float* wk = Wk + (size_t)l * Dd * Dd;
        const float* wv = Wv + (size_t)l * Dd * Dd;
        const float* w1 = W1 + (size_t)l * Dd * FF;
        const float* w2 = W2 + (size_t)l * FF * Dd;

        qkv_kernel<<<gQKV, 256>>>(x, wq, wk, wv, q, k, v);

        attn_kernel<<<dim3(Tt / 64, Hh, Bb), 128>>>(q, k, v, y);

        ln_res_kernel<<<BT, 256>>>(y, x, ln1g + l * Dd, ln1b + l * Dd, x2);

        tgemm_kernel<2><<<gF, 256>>>(x2, w1, b1 + (size_t)l * FF, ff1, FF, Dd, FF);
        tgemm_kernel<1><<<gD, 256>>>(ff1, w2, b2 + (size_t)l * Dd, y, Dd, FF, Dd);

        ln_res_kernel<<<BT, 256>>>(y, x2, ln2g + l * Dd, ln2b + l * Dd, x);
    }

    // head: padded, pre-converted B with stride VP; stores guarded to N=Vv
    tgemm_kernel<1><<<gV, 256>>>(x, wpad, headb, out, Vv, Dd, VP);

    rowloss_kernel<<<BT, 256>>>(out, tgt, rl);
    meanloss_kernel<<<1, 256>>>(rl, out + (size_t)BT * Vv);
}